// round 13
// baseline (speedup 1.0000x reference)
#include <cuda_runtime.h>
#include <cstdint>

// Problem constants
constexpr int B = 2, S = 2048, HID = 2048, NH = 16, NKV = 4, HD = 128;
constexpr int M = B * S;  // 4096 rows for all GEMMs

// fp32 scratch
__device__ float g_q[(size_t)B * S * NH * HD];     // [B,S,NH,HD]
__device__ float g_k[(size_t)B * S * NKV * HD];    // [B,S,NKV,HD]
__device__ float g_v[(size_t)B * S * NKV * HD];    // [B,S,NKV,HD]
__device__ float g_attn[(size_t)B * S * NH * HD];  // [B,S,NH*HD]
// fp16 packed (word = 2 fp16) attention-ready buffers
__device__ uint32_t g_qh[(size_t)B * S * NH * 64];        // [b][s][h][64w] roped*scale
__device__ uint32_t g_kh[(size_t)B * NKV * S * 64];       // [b][kh][s][64w] roped
__device__ uint32_t g_vh[(size_t)B * NKV * (S / 2) * 128];// [b][kh][kwp][128w] pair-packed

// ---------------- fp16 / misc helpers ----------------
__device__ __forceinline__ uint32_t cvt2h(float lo_e, float hi_e) {
    uint32_t r;
    asm("cvt.rn.f16x2.f32 %0, %1, %2;" : "=r"(r) : "f"(hi_e), "f"(lo_e));
    return r;
}
__device__ __forceinline__ void mmah(float* c, const uint32_t* a, const uint32_t* b) {
    asm volatile(
        "mma.sync.aligned.m16n8k16.row.col.f32.f16.f16.f32 "
        "{%0,%1,%2,%3}, {%4,%5,%6,%7}, {%8,%9}, {%0,%1,%2,%3};"
        : "+f"(c[0]), "+f"(c[1]), "+f"(c[2]), "+f"(c[3])
        : "r"(a[0]), "r"(a[1]), "r"(a[2]), "r"(a[3]), "r"(b[0]), "r"(b[1]));
}
__device__ __forceinline__ uint32_t smem_u32(const void* p) {
    uint32_t a;
    asm("{ .reg .u64 t; cvta.to.shared.u64 t, %1; cvt.u32.u64 %0, t; }" : "=r"(a) : "l"(p));
    return a;
}
#define CP16(dst, src) \
    asm volatile("cp.async.cg.shared.global [%0], [%1], 16;" :: "r"(dst), "l"(src) : "memory")
#define CP_COMMIT() asm volatile("cp.async.commit_group;" ::: "memory")
#define CP_WAIT1() asm volatile("cp.async.wait_group 1;" ::: "memory")
#define CP_WAIT0() asm volatile("cp.async.wait_group 0;" ::: "memory")

// ================= fp16 single-pass GEMM body (R10 config: measured fastest) =================
// 256 threads, 8 warps (2m x 4n), warp tile 64x32, CTA tile 128x128, KC=32.
// __launch_bounds__(256,1): let ptxas use ~186 regs, NO spills (R11/R12 showed
// any <=128-reg config spills or degrades; this is the proven 690us config).
constexpr int ROW_W = 20;
constexpr int TILE_W = 128 * ROW_W;
constexpr int STAGE_W = 2 * TILE_W;
constexpr int GEMM_SMEM = 2 * STAGE_W * 4;  // 40960 B
constexpr int T_A = 0, T_B = TILE_W;

__device__ __forceinline__ void gemm_body(
    const float* __restrict__ A, const float* __restrict__ Bw,
    const float* __restrict__ bias, float* __restrict__ C,
    int N, int K, int m0, int n0, uint32_t* smw)
{
    const int tid = threadIdx.x;
    const int lane = tid & 31;
    const int w = tid >> 5;
    const int wm = w & 1, wn = w >> 1;
    const int NIT = K / 32;

    float acc[4][4][4];
#pragma unroll
    for (int mt = 0; mt < 4; mt++)
#pragma unroll
        for (int nt = 0; nt < 4; nt++)
#pragma unroll
            for (int r = 0; r < 4; r++) acc[mt][nt][r] = 0.f;

    float4 pa[4], pb[4];
    auto ldg = [&](int k0) {
#pragma unroll
        for (int i = 0; i < 4; i++) {
            const int idx = tid + i * 256;
            const int r = idx >> 3, c = idx & 7;
            pa[i] = *(const float4*)(A + (size_t)(m0 + r) * K + k0 + c * 4);
            pb[i] = *(const float4*)(Bw + (size_t)(n0 + r) * K + k0 + c * 4);
        }
    };
    auto sts = [&](uint32_t* buf) {
#pragma unroll
        for (int i = 0; i < 4; i++) {
            const int idx = tid + i * 256;
            const int r = idx >> 3, c = idx & 7;
            const int off = r * ROW_W + c * 2;
            *(uint2*)&buf[T_A + off] =
                make_uint2(cvt2h(pa[i].x, pa[i].y), cvt2h(pa[i].z, pa[i].w));
            *(uint2*)&buf[T_B + off] =
                make_uint2(cvt2h(pb[i].x, pb[i].y), cvt2h(pb[i].z, pb[i].w));
        }
    };

    ldg(0);
    sts(smw);
    __syncthreads();

    const int arow = wm * 64 + (lane >> 2);
    const int brow = wn * 32 + (lane >> 2);
    const int kq = lane & 3;

    for (int it = 0; it < NIT; it++) {
        uint32_t* buf = smw + (it & 1) * STAGE_W;
        if (it + 1 < NIT) ldg((it + 1) * 32);

#pragma unroll
        for (int ks = 0; ks < 2; ks++) {
            const int kw = ks * 8 + kq;
            uint32_t ah[4][4], bh[4][2];
#pragma unroll
            for (int mt = 0; mt < 4; mt++) {
                const int base = T_A + (arow + mt * 16) * ROW_W + kw;
                ah[mt][0] = buf[base];
                ah[mt][1] = buf[base + 8 * ROW_W];
                ah[mt][2] = buf[base + 4];
                ah[mt][3] = buf[base + 8 * ROW_W + 4];
            }
#pragma unroll
            for (int nt = 0; nt < 4; nt++) {
                const int base = T_B + (brow + nt * 8) * ROW_W + kw;
                bh[nt][0] = buf[base];
                bh[nt][1] = buf[base + 4];
            }
#pragma unroll
            for (int mt = 0; mt < 4; mt++)
#pragma unroll
                for (int nt = 0; nt < 4; nt++)
                    mmah(acc[mt][nt], ah[mt], bh[nt]);
        }
        if (it + 1 < NIT) {
            sts(smw + ((it + 1) & 1) * STAGE_W);
            __syncthreads();
        }
    }

#pragma unroll
    for (int mt = 0; mt < 4; mt++) {
        const int r0 = m0 + wm * 64 + mt * 16 + (lane >> 2);
#pragma unroll
        for (int nt = 0; nt < 4; nt++) {
            const int cc = n0 + wn * 32 + nt * 8 + (lane & 3) * 2;
            float b0 = 0.f, b1 = 0.f;
            if (bias) { b0 = bias[cc]; b1 = bias[cc + 1]; }
            *(float2*)(C + (size_t)r0 * N + cc) =
                make_float2(acc[mt][nt][0] + b0, acc[mt][nt][1] + b1);
            *(float2*)(C + (size_t)(r0 + 8) * N + cc) =
                make_float2(acc[mt][nt][2] + b0, acc[mt][nt][3] + b1);
        }
    }
}

__global__ __launch_bounds__(256, 1) void gemm_qkv(
    const float* __restrict__ A,
    const float* __restrict__ Wq, const float* __restrict__ bq,
    const float* __restrict__ Wk, const float* __restrict__ bk,
    const float* __restrict__ Wv, const float* __restrict__ bv,
    float* __restrict__ qp, float* __restrict__ kp, float* __restrict__ vp)
{
    extern __shared__ uint32_t smw[];
    const int bx = blockIdx.x;
    const int m0 = blockIdx.y * 128;
    if (bx < 16) {
        gemm_body(A, Wq, bq, qp, NH * HD, HID, m0, bx * 128, smw);
    } else if (bx < 20) {
        gemm_body(A, Wk, bk, kp, NKV * HD, HID, m0, (bx - 16) * 128, smw);
    } else {
        gemm_body(A, Wv, bv, vp, NKV * HD, HID, m0, (bx - 20) * 128, smw);
    }
}

__global__ __launch_bounds__(256, 1) void gemm_h16(
    const float* __restrict__ A, const float* __restrict__ Bw,
    const float* __restrict__ bias, float* __restrict__ C,
    int N, int K)
{
    extern __shared__ uint32_t smw[];
    gemm_body(A, Bw, bias, C, N, K, blockIdx.y * 128, blockIdx.x * 128, smw);
}

// ---------------- RoPE: fp32 q/k -> fp16 packed (q pre-scaled) ----------------
__global__ void rope_kernel() {
    const int total = B * S * (NH + NKV) * 32;  // thread = 2 adjacent dims
    int idx = blockIdx.x * blockDim.x + threadIdx.x;
    if (idx >= total) return;
    const int p2 = idx & 31;          // word index within first half
    const int p = p2 * 2;
    const int h = (idx >> 5) % (NH + NKV);
    const int rem = (idx >> 5) / (NH + NKV);
    const int s = rem % S;
    const int b = rem / S;
    const double a0 = (double)s * pow(10000.0, -(double)p / 64.0);
    const double a1 = (double)s * pow(10000.0, -(double)(p + 1) / 64.0);
    double s0d, c0d, s1d, c1d;
    sincos(a0, &s0d, &c0d);
    sincos(a1, &s1d, &c1d);
    const float c0 = (float)c0d, sn0 = (float)s0d;
    const float c1 = (float)c1d, sn1 = (float)s1d;
    if (h < NH) {
        const float* base = g_q + ((size_t)((b * S + s) * NH + h)) * HD;
        const float x0 = base[p], x1 = base[p + 1];
        const float y0 = base[p + 64], y1 = base[p + 65];
        const float scale = 0.08838834764831845f;
        const float lo0 = (x0 * c0 - y0 * sn0) * scale;
        const float lo1 = (x1 * c1 - y1 * sn1) * scale;
        const float hi0 = (y0 * c0 + x0 * sn0) * scale;
        const float hi1 = (y1 * c1 + x1 * sn1) * scale;
        uint32_t* qo = g_qh + ((size_t)((b * S + s) * NH + h)) * 64;
        qo[p2] = cvt2h(lo0, lo1);
        qo[32 + p2] = cvt2h(hi0, hi1);
    } else {
        const int kh = h - NH;
        const float* base = g_k + ((size_t)((b * S + s) * NKV + kh)) * HD;
        const float x0 = base[p], x1 = base[p + 1];
        const float y0 = base[p + 64], y1 = base[p + 65];
        uint32_t* ko = g_kh + ((size_t)((b * NKV + kh) * S + s)) * 64;
        ko[p2] = cvt2h(x0 * c0 - y0 * sn0, x1 * c1 - y1 * sn1);
        ko[32 + p2] = cvt2h(y0 * c0 + x0 * sn0, y1 * c1 + x1 * sn1);
    }
}

// ---------------- V: fp32 -> fp16 pair-packed [b][kh][kwp][128w] ----------------
__global__ void vconv_kernel() {
    const int total = B * NKV * (S / 2) * 32;  // thread = one uint4 chunk
    int idx = blockIdx.x * blockDim.x + threadIdx.x;
    if (idx >= total) return;
    const int c = idx & 31, d0 = c * 4;
    const int kwp = (idx >> 5) % (S / 2);
    const int t2 = (idx >> 5) / (S / 2);
    const int kh = t2 % NKV, b = t2 / NKV;
    const float* base = g_v + ((size_t)((b * S + 2 * kwp) * NKV + kh)) * HD + d0;
    const float4 va = *(const float4*)base;
    const float4 vb = *(const float4*)(base + (size_t)NKV * HD);
    uint32_t* vo = g_vh + ((size_t)((b * NKV + kh) * (S / 2) + kwp)) * 128 + d0;
    *(uint4*)vo = make_uint4(cvt2h(va.x, vb.x), cvt2h(va.y, vb.y),
                             cvt2h(va.z, vb.z), cvt2h(va.w, vb.w));
}

// ================= Flash attention: cp.async double-buffered, register-P =================
// CTA: q-tile 64 (4 warps x 16 rows), kv-tile 64, 128 threads, 2 CTAs/SM. (R11, 146us)
constexpr int QT = 64, KT = 64;
constexpr int QROW = 68, KROW = 68, VROW = 136;
constexpr int A_Q = 0;                        // 64 x 68
constexpr int A_K0 = A_Q + QT * QROW;         // 2 stages of 64 x 68
constexpr int A_V0 = A_K0 + 2 * KT * KROW;    // 2 stages of 32 x 136
constexpr int ATTN_SMEM = (A_V0 + 2 * 32 * VROW) * 4;  // 87040 B

__global__ __launch_bounds__(128, 2) void attn_mma() {
    extern __shared__ uint32_t sw[];
    const uint32_t swb = smem_u32(sw);
    const int q0 = (gridDim.x - 1 - blockIdx.x) * QT;  // long CTAs first
    const int h = blockIdx.y, b = blockIdx.z;
    const int kh = h >> 2;
    const int tid = threadIdx.x;
    const int lane = tid & 31, w = tid >> 5;
    const int r4 = lane >> 2, cq = lane & 3;

    const uint32_t* kbase = g_kh + ((size_t)(b * NKV + kh)) * S * 64;
    const uint32_t* vbase = g_vh + ((size_t)(b * NKV + kh)) * (S / 2) * 128;

    auto copyKV = [&](int t, int st) {
        const uint32_t kdst0 = swb + (A_K0 + st * KT * KROW) * 4;
        const uint32_t vdst0 = swb + (A_V0 + st * 32 * VROW) * 4;
        const uint32_t* kg = kbase + (size_t)t * KT * 64;
        const uint32_t* vg = vbase + (size_t)t * 32 * 128;
#pragma unroll
        for (int i = 0; i < 8; i++) {
            const int c = tid + i * 128;
            const int kr = c >> 4, kc = c & 15;
            CP16(kdst0 + (kr * KROW + kc * 4) * 4, kg + kr * 64 + kc * 4);
            const int vr = c >> 5, vc = c & 31;
            CP16(vdst0 + (vr * VROW + vc * 4) * 4, vg + vr * 128 + vc * 4);
        }
    };

    // prologue: Q + tile0 as one group
    {
        const uint32_t* qg = g_qh;
#pragma unroll
        for (int i = 0; i < 8; i++) {
            const int c = tid + i * 128;
            const int r = c >> 4, cc = c & 15;
            CP16(swb + (A_Q + r * QROW + cc * 4) * 4,
                 qg + ((size_t)((b * S + q0 + r) * NH + h)) * 64 + cc * 4);
        }
        copyKV(0, 0);
        CP_COMMIT();
    }

    float o[16][4];
#pragma unroll
    for (int nt = 0; nt < 16; nt++)
#pragma unroll
        for (int r = 0; r < 4; r++) o[nt][r] = 0.f;
    float m0 = -1e30f, m1 = -1e30f, l0 = 0.f, l1 = 0.f;

    const int ntiles = (q0 >> 6) + 1;

    for (int t = 0; t < ntiles; t++) {
        if (t + 1 < ntiles) {
            copyKV(t + 1, (t + 1) & 1);
            CP_COMMIT();
            CP_WAIT1();
        } else {
            CP_WAIT0();
        }
        __syncthreads();
        const int kb = A_K0 + (t & 1) * KT * KROW;
        const int vb = A_V0 + (t & 1) * 32 * VROW;

        // scores: S = Qs * Ks^T
        float sc[8][4];
#pragma unroll
        for (int nt = 0; nt < 8; nt++)
#pragma unroll
            for (int r = 0; r < 4; r++) sc[nt][r] = 0.f;
#pragma unroll
        for (int ks = 0; ks < 8; ks++) {
            uint32_t ah[4];
            const int base = A_Q + (w * 16 + r4) * QROW + ks * 8 + cq;
            ah[0] = sw[base];
            ah[1] = sw[base + 8 * QROW];
            ah[2] = sw[base + 4];
            ah[3] = sw[base + 8 * QROW + 4];
#pragma unroll
            for (int nt = 0; nt < 8; nt++) {
                const int nb = kb + (nt * 8 + r4) * KROW + ks * 8 + cq;
                uint32_t bh[2] = {sw[nb], sw[nb + 4]};
                mmah(sc[nt], ah, bh);
            }
        }
        // causal mask: only diagonal tile
        if (t == ntiles - 1) {
            const int n0 = t * KT;
            const int row0 = q0 + w * 16 + r4, row1 = row0 + 8;
#pragma unroll
            for (int nt = 0; nt < 8; nt++) {
                const int col0 = n0 + nt * 8 + 2 * cq;
                if (col0 > row0) sc[nt][0] = -1e30f;
                if (col0 + 1 > row0) sc[nt][1] = -1e30f;
                if (col0 > row1) sc[nt][2] = -1e30f;
                if (col0 + 1 > row1) sc[nt][3] = -1e30f;
            }
        }
        // online softmax
        float rx0 = -1e30f, rx1 = -1e30f;
#pragma unroll
        for (int nt = 0; nt < 8; nt++) {
            rx0 = fmaxf(rx0, fmaxf(sc[nt][0], sc[nt][1]));
            rx1 = fmaxf(rx1, fmaxf(sc[nt][2], sc[nt][3]));
        }
        rx0 = fmaxf(rx0, __shfl_xor_sync(0xffffffffu, rx0, 1));
        rx0 = fmaxf(rx0, __shfl_xor_sync(0xffffffffu, rx0, 2));
        rx1 = fmaxf(rx1, __shfl_xor_sync(0xffffffffu, rx1, 1));
        rx1 = fmaxf(rx1, __shfl_xor_sync(0xffffffffu, rx1, 2));
        const float mn0 = fmaxf(m0, rx0), mn1 = fmaxf(m1, rx1);
        const float f0 = __expf(m0 - mn0), f1 = __expf(m1 - mn1);
        float rs0 = 0.f, rs1 = 0.f;
#pragma unroll
        for (int nt = 0; nt < 8; nt++) {
            sc[nt][0] = __expf(sc[nt][0] - mn0);
            sc[nt][1] = __expf(sc[nt][1] - mn0);
            sc[nt][2] = __expf(sc[nt][2] - mn1);
            sc[nt][3] = __expf(sc[nt][3] - mn1);
            rs0 += sc[nt][0] + sc[nt][1];
            rs1 += sc[nt][2] + sc[nt][3];
        }
        rs0 += __shfl_xor_sync(0xffffffffu, rs0, 1);
        rs0 += __shfl_xor_sync(0xffffffffu, rs0, 2);
        rs1 += __shfl_xor_sync(0xffffffffu, rs1, 1);
        rs1 += __shfl_xor_sync(0xffffffffu, rs1, 2);
        l0 = l0 * f0 + rs0;
        l1 = l1 * f1 + rs1;
        m0 = mn0; m1 = mn1;
#pragma unroll
        for (int nt = 0; nt < 16; nt++) {
            o[nt][0] *= f0; o[nt][1] *= f0;
            o[nt][2] *= f1; o[nt][3] *= f1;
        }
        // O += P * V, P packed straight from registers (C-frag == A-frag layout)
#pragma unroll
        for (int ks = 0; ks < 4; ks++) {
            uint32_t ah[4];
            ah[0] = cvt2h(sc[2 * ks][0], sc[2 * ks][1]);
            ah[1] = cvt2h(sc[2 * ks][2], sc[2 * ks][3]);
            ah[2] = cvt2h(sc[2 * ks + 1][0], sc[2 * ks + 1][1]);
            ah[3] = cvt2h(sc[2 * ks + 1][2], sc[2 * ks + 1][3]);
#pragma unroll
            for (int nt = 0; nt < 16; nt++) {
                const int vb0 = vb + (ks * 8 + cq) * VROW + nt * 8 + r4;
                uint32_t bh[2] = {sw[vb0], sw[vb0 + 4 * VROW]};
                mmah(o[nt], ah, bh);
            }
        }
        __syncthreads();  // all warps done with stage (t&1) before overwrite
    }

    // normalize + write
    const float i0 = 1.0f / l0, i1 = 1.0f / l1;
    const size_t ro0 = ((size_t)((b * S + q0 + w * 16 + r4) * NH + h)) * HD;
    const size_t ro1 = ((size_t)((b * S + q0 + w * 16 + r4 + 8) * NH + h)) * HD;
#pragma unroll
    for (int nt = 0; nt < 16; nt++) {
        const int col = nt * 8 + 2 * cq;
        *(float2*)(g_attn + ro0 + col) = make_float2(o[nt][0] * i0, o[nt][1] * i0);
        *(float2*)(g_attn + ro1 + col) = make_float2(o[nt][2] * i1, o[nt][3] * i1);
    }
}

// ---------------- launch ----------------
extern "C" void kernel_launch(void* const* d_in, const int* in_sizes, int n_in,
                              void* d_out, int out_size) {
    const float* hs = (const float*)d_in[0];
    // d_in[1] = attention_mask: pure causal triu(-1e9, k=1) -> applied analytically
    const float* Wq = (const float*)d_in[2];
    const float* bq = (const float*)d_in[3];
    const float* Wk = (const float*)d_in[4];
    const float* bk = (const float*)d_in[5];
    const float* Wv = (const float*)d_in[6];
    const float* bv = (const float*)d_in[7];
    const float* Wo = (const float*)d_in[8];
    float* out = (float*)d_out;

    float *qp, *kp, *vp, *ap;
    cudaGetSymbolAddress((void**)&qp, g_q);
    cudaGetSymbolAddress((void**)&kp, g_k);
    cudaGetSymbolAddress((void**)&vp, g_v);
    cudaGetSymbolAddress((void**)&ap, g_attn);

    cudaFuncSetAttribute(gemm_qkv, cudaFuncAttributeMaxDynamicSharedMemorySize, GEMM_SMEM);
    cudaFuncSetAttribute(gemm_h16, cudaFuncAttributeMaxDynamicSharedMemorySize, GEMM_SMEM);
    cudaFuncSetAttribute(attn_mma, cudaFuncAttributeMaxDynamicSharedMemorySize, ATTN_SMEM);

    // Fused QKV projection (R10 config: 256 threads, no reg cap)
    gemm_qkv<<<dim3(24, M / 128), 256, GEMM_SMEM>>>(hs, Wq, bq, Wk, bk, Wv, bv, qp, kp, vp);

    // RoPE -> fp16 packed q (pre-scaled) / k ; V -> fp16 pair-packed
    const int rope_total = B * S * (NH + NKV) * 32;
    rope_kernel<<<(rope_total + 255) / 256, 256>>>();
    const int vconv_total = B * NKV * (S / 2) * 32;
    vconv_kernel<<<(vconv_total + 255) / 256, 256>>>();

    // Flash attention: cp.async double-buffered K/V, register-P
    attn_mma<<<dim3(S / QT, NH, B), 128, ATTN_SMEM>>>();

    // Output projection (R10 config)
    gemm_h16<<<dim3(HID / 128, M / 128), 256, GEMM_SMEM>>>(ap, Wo, nullptr, out, HID, NH * HD);
}

// round 14
// speedup vs baseline: 1.0683x; 1.0683x over previous
#include <cuda_runtime.h>
#include <cstdint>

// Problem constants
constexpr int B = 2, S = 2048, HID = 2048, NH = 16, NKV = 4, HD = 128;
constexpr int M = B * S;
constexpr int KW = HID / 2;  // 1024 fp16-pair words per GEMM row (K=2048)

// fp32 scratch (rope/vconv inputs)
__device__ float g_q[(size_t)B * S * NH * HD];
__device__ float g_k[(size_t)B * S * NKV * HD];
__device__ float g_v[(size_t)B * S * NKV * HD];
// fp16 packed (1 word = 2 fp16) GEMM operands
__device__ uint32_t g_hsh[(size_t)M * KW];          // hidden_states
__device__ uint32_t g_wqh[(size_t)(NH * HD) * KW];
__device__ uint32_t g_wkh[(size_t)(NKV * HD) * KW];
__device__ uint32_t g_wvh[(size_t)(NKV * HD) * KW];
__device__ uint32_t g_woh[(size_t)HID * KW];
__device__ uint32_t g_ah[(size_t)M * KW];           // attention output (fp16)
// fp16 packed attention-ready buffers
__device__ uint32_t g_qh[(size_t)B * S * NH * 64];
__device__ uint32_t g_kh[(size_t)B * NKV * S * 64];
__device__ uint32_t g_vh[(size_t)B * NKV * (S / 2) * 128];

// ---------------- helpers ----------------
__device__ __forceinline__ uint32_t cvt2h(float lo_e, float hi_e) {
    uint32_t r;
    asm("cvt.rn.f16x2.f32 %0, %1, %2;" : "=r"(r) : "f"(hi_e), "f"(lo_e));
    return r;
}
__device__ __forceinline__ void mmah(float* c, const uint32_t* a, const uint32_t* b) {
    asm volatile(
        "mma.sync.aligned.m16n8k16.row.col.f32.f16.f16.f32 "
        "{%0,%1,%2,%3}, {%4,%5,%6,%7}, {%8,%9}, {%0,%1,%2,%3};"
        : "+f"(c[0]), "+f"(c[1]), "+f"(c[2]), "+f"(c[3])
        : "r"(a[0]), "r"(a[1]), "r"(a[2]), "r"(a[3]), "r"(b[0]), "r"(b[1]));
}
__device__ __forceinline__ uint32_t smem_u32(const void* p) {
    uint32_t a;
    asm("{ .reg .u64 t; cvta.to.shared.u64 t, %1; cvt.u32.u64 %0, t; }" : "=r"(a) : "l"(p));
    return a;
}
#define CP16(dst, src) \
    asm volatile("cp.async.cg.shared.global [%0], [%1], 16;" :: "r"(dst), "l"(src) : "memory")
#define CP_COMMIT() asm volatile("cp.async.commit_group;" ::: "memory")
#define CP_WAIT0() asm volatile("cp.async.wait_group 0;" ::: "memory")
#define CP_WAIT1() asm volatile("cp.async.wait_group 1;" ::: "memory")
#define CP_WAIT3() asm volatile("cp.async.wait_group 3;" ::: "memory")

// ---------------- fp32 -> fp16 pack (all GEMM operands, one launch) ----------------
constexpr int NW_HS = M * KW;                  // 4194304
constexpr int NW_WQ = NH * HD * KW;            // 2097152
constexpr int NW_WK = NKV * HD * KW;           // 524288
constexpr int NW_WV = NW_WK;
constexpr int NW_WO = HID * KW;                // 2097152
constexpr int NW_TOT = NW_HS + NW_WQ + NW_WK + NW_WV + NW_WO;

__global__ void packh_kernel(const float* __restrict__ hs, const float* __restrict__ Wq,
                             const float* __restrict__ Wk, const float* __restrict__ Wv,
                             const float* __restrict__ Wo) {
    int i = blockIdx.x * blockDim.x + threadIdx.x;
    if (i >= NW_TOT) return;
    const float* src;
    uint32_t* dst;
    int j = i;
    if (j < NW_HS) { src = hs; dst = g_hsh; }
    else if ((j -= NW_HS) < NW_WQ) { src = Wq; dst = g_wqh; }
    else if ((j -= NW_WQ) < NW_WK) { src = Wk; dst = g_wkh; }
    else if ((j -= NW_WK) < NW_WV) { src = Wv; dst = g_wvh; }
    else { j -= NW_WV; src = Wo; dst = g_woh; }
    const float2 v = *(const float2*)(src + 2 * (size_t)j);
    dst[j] = cvt2h(v.x, v.y);
}

// ================= fp16 GEMM, 4-stage cp.async =================
// 256 threads, 8 warps (2m x 4n), warp tile 64x32, CTA tile 128x128, KC=32.
constexpr int ROW_W = 20;                    // 16 data words + 4 pad (80B: 16B-aligned)
constexpr int TILE_W = 128 * ROW_W;
constexpr int STAGE_W = 2 * TILE_W;          // A + B
constexpr int NSTAGE = 4;
constexpr int GEMM_SMEM = NSTAGE * STAGE_W * 4;  // 81920 B
constexpr int T_A = 0, T_B = TILE_W;

__device__ __forceinline__ void gemm_body(
    const uint32_t* __restrict__ A, const uint32_t* __restrict__ Bw,
    const float* __restrict__ bias, float* __restrict__ C,
    int N, int m0, int n0, uint32_t* smw, uint32_t swb)
{
    const int tid = threadIdx.x;
    const int lane = tid & 31;
    const int w = tid >> 5;
    const int wm = w & 1, wn = w >> 1;
    const int NIT = KW / 16;  // 64 chunks of 16 words (32 fp16)

    float acc[4][4][4];
#pragma unroll
    for (int mt = 0; mt < 4; mt++)
#pragma unroll
        for (int nt = 0; nt < 4; nt++)
#pragma unroll
            for (int r = 0; r < 4; r++) acc[mt][nt][r] = 0.f;

    // stage copy: A tile 128x16w + B tile 128x16w, 16B chunks, 4/thread
    auto cpstage = [&](int it, int st) {
        const uint32_t ad = swb + (st * STAGE_W + T_A) * 4;
        const uint32_t bd = swb + (st * STAGE_W + T_B) * 4;
        const int k0 = it * 16;
#pragma unroll
        for (int i = 0; i < 2; i++) {
            const int idx = tid + i * 256;
            const int r = idx >> 2, c = idx & 3;
            CP16(ad + (r * ROW_W + c * 4) * 4, A + (size_t)(m0 + r) * KW + k0 + c * 4);
            CP16(bd + (r * ROW_W + c * 4) * 4, Bw + (size_t)(n0 + r) * KW + k0 + c * 4);
        }
    };

    // prologue: stages 0..2
#pragma unroll
    for (int s = 0; s < NSTAGE - 1; s++) {
        cpstage(s, s);
        CP_COMMIT();
    }

    const int arow = wm * 64 + (lane >> 2);
    const int brow = wn * 32 + (lane >> 2);
    const int kq = lane & 3;

    for (int it = 0; it < NIT; it++) {
        if (it + NSTAGE - 1 < NIT) cpstage(it + NSTAGE - 1, (it + NSTAGE - 1) & 3);
        CP_COMMIT();  // empty group at tail keeps wait count uniform
        CP_WAIT3();
        __syncthreads();
        uint32_t* buf = smw + (it & 3) * STAGE_W;

#pragma unroll
        for (int ks = 0; ks < 2; ks++) {
            const int kw = ks * 8 + kq;
            uint32_t ah[4][4], bh[4][2];
#pragma unroll
            for (int mt = 0; mt < 4; mt++) {
                const int base = T_A + (arow + mt * 16) * ROW_W + kw;
                ah[mt][0] = buf[base];
                ah[mt][1] = buf[base + 8 * ROW_W];
                ah[mt][2] = buf[base + 4];
                ah[mt][3] = buf[base + 8 * ROW_W + 4];
            }
#pragma unroll
            for (int nt = 0; nt < 4; nt++) {
                const int base = T_B + (brow + nt * 8) * ROW_W + kw;
                bh[nt][0] = buf[base];
                bh[nt][1] = buf[base + 4];
            }
#pragma unroll
            for (int mt = 0; mt < 4; mt++)
#pragma unroll
                for (int nt = 0; nt < 4; nt++)
                    mmah(acc[mt][nt], ah[mt], bh[nt]);
        }
        __syncthreads();  // all warps done with buf before it is re-filled
    }

#pragma unroll
    for (int mt = 0; mt < 4; mt++) {
        const int r0 = m0 + wm * 64 + mt * 16 + (lane >> 2);
#pragma unroll
        for (int nt = 0; nt < 4; nt++) {
            const int cc = n0 + wn * 32 + nt * 8 + (lane & 3) * 2;
            float b0 = 0.f, b1 = 0.f;
            if (bias) { b0 = bias[cc]; b1 = bias[cc + 1]; }
            *(float2*)(C + (size_t)r0 * N + cc) =
                make_float2(acc[mt][nt][0] + b0, acc[mt][nt][1] + b1);
            *(float2*)(C + (size_t)(r0 + 8) * N + cc) =
                make_float2(acc[mt][nt][2] + b0, acc[mt][nt][3] + b1);
        }
    }
}

__global__ __launch_bounds__(256, 1) void gemm_qkv(
    const float* __restrict__ bq, const float* __restrict__ bk,
    const float* __restrict__ bv,
    float* __restrict__ qp, float* __restrict__ kp, float* __restrict__ vp)
{
    extern __shared__ uint32_t smw[];
    const uint32_t swb = smem_u32(smw);
    const int bx = blockIdx.x;
    const int m0 = blockIdx.y * 128;
    if (bx < 16) {
        gemm_body(g_hsh, g_wqh, bq, qp, NH * HD, m0, bx * 128, smw, swb);
    } else if (bx < 20) {
        gemm_body(g_hsh, g_wkh, bk, kp, NKV * HD, m0, (bx - 16) * 128, smw, swb);
    } else {
        gemm_body(g_hsh, g_wvh, bv, vp, NKV * HD, m0, (bx - 20) * 128, smw, swb);
    }
}

__global__ __launch_bounds__(256, 1) void gemm_o(float* __restrict__ C) {
    extern __shared__ uint32_t smw[];
    const uint32_t swb = smem_u32(smw);
    gemm_body(g_ah, g_woh, nullptr, C, HID, blockIdx.y * 128, blockIdx.x * 128, smw, swb);
}

// ---------------- RoPE: fp32 q/k -> fp16 packed (q pre-scaled) ----------------
__global__ void rope_kernel() {
    const int total = B * S * (NH + NKV) * 32;
    int idx = blockIdx.x * blockDim.x + threadIdx.x;
    if (idx >= total) return;
    const int p2 = idx & 31;
    const int p = p2 * 2;
    const int h = (idx >> 5) % (NH + NKV);
    const int rem = (idx >> 5) / (NH + NKV);
    const int s = rem % S;
    const int b = rem / S;
    const double a0 = (double)s * pow(10000.0, -(double)p / 64.0);
    const double a1 = (double)s * pow(10000.0, -(double)(p + 1) / 64.0);
    double s0d, c0d, s1d, c1d;
    sincos(a0, &s0d, &c0d);
    sincos(a1, &s1d, &c1d);
    const float c0 = (float)c0d, sn0 = (float)s0d;
    const float c1 = (float)c1d, sn1 = (float)s1d;
    if (h < NH) {
        const float* base = g_q + ((size_t)((b * S + s) * NH + h)) * HD;
        const float x0 = base[p], x1 = base[p + 1];
        const float y0 = base[p + 64], y1 = base[p + 65];
        const float scale = 0.08838834764831845f;
        uint32_t* qo = g_qh + ((size_t)((b * S + s) * NH + h)) * 64;
        qo[p2] = cvt2h((x0 * c0 - y0 * sn0) * scale, (x1 * c1 - y1 * sn1) * scale);
        qo[32 + p2] = cvt2h((y0 * c0 + x0 * sn0) * scale, (y1 * c1 + x1 * sn1) * scale);
    } else {
        const int kh = h - NH;
        const float* base = g_k + ((size_t)((b * S + s) * NKV + kh)) * HD;
        const float x0 = base[p], x1 = base[p + 1];
        const float y0 = base[p + 64], y1 = base[p + 65];
        uint32_t* ko = g_kh + ((size_t)((b * NKV + kh) * S + s)) * 64;
        ko[p2] = cvt2h(x0 * c0 - y0 * sn0, x1 * c1 - y1 * sn1);
        ko[32 + p2] = cvt2h(y0 * c0 + x0 * sn0, y1 * c1 + x1 * sn1);
    }
}

// ---------------- V: fp32 -> fp16 pair-packed ----------------
__global__ void vconv_kernel() {
    const int total = B * NKV * (S / 2) * 32;
    int idx = blockIdx.x * blockDim.x + threadIdx.x;
    if (idx >= total) return;
    const int c = idx & 31, d0 = c * 4;
    const int kwp = (idx >> 5) % (S / 2);
    const int t2 = (idx >> 5) / (S / 2);
    const int kh = t2 % NKV, b = t2 / NKV;
    const float* base = g_v + ((size_t)((b * S + 2 * kwp) * NKV + kh)) * HD + d0;
    const float4 va = *(const float4*)base;
    const float4 vb = *(const float4*)(base + (size_t)NKV * HD);
    uint32_t* vo = g_vh + ((size_t)((b * NKV + kh) * (S / 2) + kwp)) * 128 + d0;
    *(uint4*)vo = make_uint4(cvt2h(va.x, vb.x), cvt2h(va.y, vb.y),
                             cvt2h(va.z, vb.z), cvt2h(va.w, vb.w));
}

// ================= Flash attention (R11, 146us) — output now fp16 to g_ah =================
constexpr int QT = 64, KT = 64;
constexpr int QROW = 68, KROW = 68, VROW = 136;
constexpr int A_Q = 0;
constexpr int A_K0 = A_Q + QT * QROW;
constexpr int A_V0 = A_K0 + 2 * KT * KROW;
constexpr int ATTN_SMEM = (A_V0 + 2 * 32 * VROW) * 4;  // 87040 B

__global__ __launch_bounds__(128, 2) void attn_mma() {
    extern __shared__ uint32_t sw[];
    const uint32_t swb = smem_u32(sw);
    const int q0 = (gridDim.x - 1 - blockIdx.x) * QT;
    const int h = blockIdx.y, b = blockIdx.z;
    const int kh = h >> 2;
    const int tid = threadIdx.x;
    const int lane = tid & 31, w = tid >> 5;
    const int r4 = lane >> 2, cq = lane & 3;

    const uint32_t* kbase = g_kh + ((size_t)(b * NKV + kh)) * S * 64;
    const uint32_t* vbase = g_vh + ((size_t)(b * NKV + kh)) * (S / 2) * 128;

    auto copyKV = [&](int t, int st) {
        const uint32_t kdst0 = swb + (A_K0 + st * KT * KROW) * 4;
        const uint32_t vdst0 = swb + (A_V0 + st * 32 * VROW) * 4;
        const uint32_t* kg = kbase + (size_t)t * KT * 64;
        const uint32_t* vg = vbase + (size_t)t * 32 * 128;
#pragma unroll
        for (int i = 0; i < 8; i++) {
            const int c = tid + i * 128;
            const int kr = c >> 4, kc = c & 15;
            CP16(kdst0 + (kr * KROW + kc * 4) * 4, kg + kr * 64 + kc * 4);
            const int vr = c >> 5, vc = c & 31;
            CP16(vdst0 + (vr * VROW + vc * 4) * 4, vg + vr * 128 + vc * 4);
        }
    };

    {
#pragma unroll
        for (int i = 0; i < 8; i++) {
            const int c = tid + i * 128;
            const int r = c >> 4, cc = c & 15;
            CP16(swb + (A_Q + r * QROW + cc * 4) * 4,
                 g_qh + ((size_t)((b * S + q0 + r) * NH + h)) * 64 + cc * 4);
        }
        copyKV(0, 0);
        CP_COMMIT();
    }

    float o[16][4];
#pragma unroll
    for (int nt = 0; nt < 16; nt++)
#pragma unroll
        for (int r = 0; r < 4; r++) o[nt][r] = 0.f;
    float m0 = -1e30f, m1 = -1e30f, l0 = 0.f, l1 = 0.f;

    const int ntiles = (q0 >> 6) + 1;

    for (int t = 0; t < ntiles; t++) {
        if (t + 1 < ntiles) {
            copyKV(t + 1, (t + 1) & 1);
            CP_COMMIT();
            CP_WAIT1();
        } else {
            CP_WAIT0();
        }
        __syncthreads();
        const int kb = A_K0 + (t & 1) * KT * KROW;
        const int vb = A_V0 + (t & 1) * 32 * VROW;

        float sc[8][4];
#pragma unroll
        for (int nt = 0; nt < 8; nt++)
#pragma unroll
            for (int r = 0; r < 4; r++) sc[nt][r] = 0.f;
#pragma unroll
        for (int ks = 0; ks < 8; ks++) {
            uint32_t ah[4];
            const int base = A_Q + (w * 16 + r4) * QROW + ks * 8 + cq;
            ah[0] = sw[base];
            ah[1] = sw[base + 8 * QROW];
            ah[2] = sw[base + 4];
            ah[3] = sw[base + 8 * QROW + 4];
#pragma unroll
            for (int nt = 0; nt < 8; nt++) {
                const int nb = kb + (nt * 8 + r4) * KROW + ks * 8 + cq;
                uint32_t bh[2] = {sw[nb], sw[nb + 4]};
                mmah(sc[nt], ah, bh);
            }
        }
        if (t == ntiles - 1) {
            const int n0 = t * KT;
            const int row0 = q0 + w * 16 + r4, row1 = row0 + 8;
#pragma unroll
            for (int nt = 0; nt < 8; nt++) {
                const int col0 = n0 + nt * 8 + 2 * cq;
                if (col0 > row0) sc[nt][0] = -1e30f;
                if (col0 + 1 > row0) sc[nt][1] = -1e30f;
                if (col0 > row1) sc[nt][2] = -1e30f;
                if (col0 + 1 > row1) sc[nt][3] = -1e30f;
            }
        }
        float rx0 = -1e30f, rx1 = -1e30f;
#pragma unroll
        for (int nt = 0; nt < 8; nt++) {
            rx0 = fmaxf(rx0, fmaxf(sc[nt][0], sc[nt][1]));
            rx1 = fmaxf(rx1, fmaxf(sc[nt][2], sc[nt][3]));
        }
        rx0 = fmaxf(rx0, __shfl_xor_sync(0xffffffffu, rx0, 1));
        rx0 = fmaxf(rx0, __shfl_xor_sync(0xffffffffu, rx0, 2));
        rx1 = fmaxf(rx1, __shfl_xor_sync(0xffffffffu, rx1, 1));
        rx1 = fmaxf(rx1, __shfl_xor_sync(0xffffffffu, rx1, 2));
        const float mn0 = fmaxf(m0, rx0), mn1 = fmaxf(m1, rx1);
        const float f0 = __expf(m0 - mn0), f1 = __expf(m1 - mn1);
        float rs0 = 0.f, rs1 = 0.f;
#pragma unroll
        for (int nt = 0; nt < 8; nt++) {
            sc[nt][0] = __expf(sc[nt][0] - mn0);
            sc[nt][1] = __expf(sc[nt][1] - mn0);
            sc[nt][2] = __expf(sc[nt][2] - mn1);
            sc[nt][3] = __expf(sc[nt][3] - mn1);
            rs0 += sc[nt][0] + sc[nt][1];
            rs1 += sc[nt][2] + sc[nt][3];
        }
        rs0 += __shfl_xor_sync(0xffffffffu, rs0, 1);
        rs0 += __shfl_xor_sync(0xffffffffu, rs0, 2);
        rs1 += __shfl_xor_sync(0xffffffffu, rs1, 1);
        rs1 += __shfl_xor_sync(0xffffffffu, rs1, 2);
        l0 = l0 * f0 + rs0;
        l1 = l1 * f1 + rs1;
        m0 = mn0; m1 = mn1;
#pragma unroll
        for (int nt = 0; nt < 16; nt++) {
            o[nt][0] *= f0; o[nt][1] *= f0;
            o[nt][2] *= f1; o[nt][3] *= f1;
        }
#pragma unroll
        for (int ks = 0; ks < 4; ks++) {
            uint32_t ah[4];
            ah[0] = cvt2h(sc[2 * ks][0], sc[2 * ks][1]);
            ah[1] = cvt2h(sc[2 * ks][2], sc[2 * ks][3]);
            ah[2] = cvt2h(sc[2 * ks + 1][0], sc[2 * ks + 1][1]);
            ah[3] = cvt2h(sc[2 * ks + 1][2], sc[2 * ks + 1][3]);
#pragma unroll
            for (int nt = 0; nt < 16; nt++) {
                const int vb0 = vb + (ks * 8 + cq) * VROW + nt * 8 + r4;
                uint32_t bh[2] = {sw[vb0], sw[vb0 + 4 * VROW]};
                mmah(o[nt], ah, bh);
            }
        }
        __syncthreads();
    }

    // normalize + write fp16 packed rows of g_ah [M][1024w]
    const float i0 = 1.0f / l0, i1 = 1.0f / l1;
    uint32_t* a0 = g_ah + (size_t)(b * S + q0 + w * 16 + r4) * KW + h * 64;
    uint32_t* a1 = g_ah + (size_t)(b * S + q0 + w * 16 + r4 + 8) * KW + h * 64;
#pragma unroll
    for (int nt = 0; nt < 16; nt++) {
        a0[nt * 4 + cq] = cvt2h(o[nt][0] * i0, o[nt][1] * i0);
        a1[nt * 4 + cq] = cvt2h(o[nt][2] * i1, o[nt][3] * i1);
    }
}

// ---------------- launch ----------------
extern "C" void kernel_launch(void* const* d_in, const int* in_sizes, int n_in,
                              void* d_out, int out_size) {
    const float* hs = (const float*)d_in[0];
    // d_in[1] = attention_mask: pure causal -> applied analytically
    const float* Wq = (const float*)d_in[2];
    const float* bq = (const float*)d_in[3];
    const float* Wk = (const float*)d_in[4];
    const float* bk = (const float*)d_in[5];
    const float* Wv = (const float*)d_in[6];
    const float* bv = (const float*)d_in[7];
    const float* Wo = (const float*)d_in[8];
    float* out = (float*)d_out;

    float *qp, *kp, *vp;
    cudaGetSymbolAddress((void**)&qp, g_q);
    cudaGetSymbolAddress((void**)&kp, g_k);
    cudaGetSymbolAddress((void**)&vp, g_v);

    cudaFuncSetAttribute(gemm_qkv, cudaFuncAttributeMaxDynamicSharedMemorySize, GEMM_SMEM);
    cudaFuncSetAttribute(gemm_o, cudaFuncAttributeMaxDynamicSharedMemorySize, GEMM_SMEM);
    cudaFuncSetAttribute(attn_mma, cudaFuncAttributeMaxDynamicSharedMemorySize, ATTN_SMEM);

    // Pack all fp32 GEMM operands to fp16 once
    packh_kernel<<<(NW_TOT + 255) / 256, 256>>>(hs, Wq, Wk, Wv, Wo);

    // Fused QKV projection (fp16 operands, 4-stage cp.async)
    gemm_qkv<<<dim3(24, M / 128), 256, GEMM_SMEM>>>(bq, bk, bv, qp, kp, vp);

    // RoPE / V conversion to attention-ready fp16 layouts
    const int rope_total = B * S * (NH + NKV) * 32;
    rope_kernel<<<(rope_total + 255) / 256, 256>>>();
    const int vconv_total = B * NKV * (S / 2) * 32;
    vconv_kernel<<<(vconv_total + 255) / 256, 256>>>();

    // Flash attention (writes fp16 g_ah)
    attn_mma<<<dim3(S / QT, NH, B), 128, ATTN_SMEM>>>();

    // Output projection (fp16 operands, 4-stage cp.async)
    gemm_o<<<dim3(HID / 128, M / 128), 256, GEMM_SMEM>>>(out);
}

// round 15
// speedup vs baseline: 2.7700x; 2.5930x over previous
#include <cuda_runtime.h>
#include <cstdint>

// Problem constants
constexpr int B = 2, S = 2048, HID = 2048, NH = 16, NKV = 4, HD = 128;
constexpr int M = B * S;
constexpr int KW = HID / 2;  // 1024 fp16-pair words per GEMM row (K=2048)

// fp32 scratch (rope/vconv inputs)
__device__ float g_q[(size_t)B * S * NH * HD];
__device__ float g_k[(size_t)B * S * NKV * HD];
__device__ float g_v[(size_t)B * S * NKV * HD];
// RoPE tables (fp32, computed once in double)
__device__ float g_cos[(size_t)S * 64];
__device__ float g_sin[(size_t)S * 64];
// fp16 packed (1 word = 2 fp16) GEMM operands
__device__ uint32_t g_hsh[(size_t)M * KW];          // hidden_states
__device__ uint32_t g_wqh[(size_t)(NH * HD) * KW];
__device__ uint32_t g_wkh[(size_t)(NKV * HD) * KW];
__device__ uint32_t g_wvh[(size_t)(NKV * HD) * KW];
__device__ uint32_t g_woh[(size_t)HID * KW];
__device__ uint32_t g_ah[(size_t)M * KW];           // attention output (fp16)
// fp16 packed attention-ready buffers
__device__ uint32_t g_qh[(size_t)B * S * NH * 64];
__device__ uint32_t g_kh[(size_t)B * NKV * S * 64];
__device__ uint32_t g_vh[(size_t)B * NKV * (S / 2) * 128];

// ---------------- helpers ----------------
__device__ __forceinline__ uint32_t cvt2h(float lo_e, float hi_e) {
    uint32_t r;
    asm("cvt.rn.f16x2.f32 %0, %1, %2;" : "=r"(r) : "f"(hi_e), "f"(lo_e));
    return r;
}
__device__ __forceinline__ void mmah(float* c, const uint32_t* a, const uint32_t* b) {
    asm volatile(
        "mma.sync.aligned.m16n8k16.row.col.f32.f16.f16.f32 "
        "{%0,%1,%2,%3}, {%4,%5,%6,%7}, {%8,%9}, {%0,%1,%2,%3};"
        : "+f"(c[0]), "+f"(c[1]), "+f"(c[2]), "+f"(c[3])
        : "r"(a[0]), "r"(a[1]), "r"(a[2]), "r"(a[3]), "r"(b[0]), "r"(b[1]));
}
__device__ __forceinline__ uint32_t smem_u32(const void* p) {
    uint32_t a;
    asm("{ .reg .u64 t; cvta.to.shared.u64 t, %1; cvt.u32.u64 %0, t; }" : "=r"(a) : "l"(p));
    return a;
}
#define CP16(dst, src) \
    asm volatile("cp.async.cg.shared.global [%0], [%1], 16;" :: "r"(dst), "l"(src) : "memory")
#define CP_COMMIT() asm volatile("cp.async.commit_group;" ::: "memory")
#define CP_WAIT0() asm volatile("cp.async.wait_group 0;" ::: "memory")
#define CP_WAIT1() asm volatile("cp.async.wait_group 1;" ::: "memory")
#define CP_WAIT3() asm volatile("cp.async.wait_group 3;" ::: "memory")

// ---------------- RoPE table: double math ONCE per (s,p) ----------------
__global__ void rope_table_kernel() {
    int idx = blockIdx.x * blockDim.x + threadIdx.x;
    if (idx >= S * 64) return;
    const int p = idx & 63, s = idx >> 6;
    const double ang = (double)s * pow(10000.0, -(double)p / 64.0);
    double sd, cd;
    sincos(ang, &sd, &cd);
    g_cos[idx] = (float)cd;   // identical rounding to previous in-thread compute
    g_sin[idx] = (float)sd;
}

// ---------------- fp32 -> fp16 pack: weights ----------------
constexpr int NW_WQ = NH * HD * KW;
constexpr int NW_WK = NKV * HD * KW;
constexpr int NW_WV = NW_WK;
constexpr int NW_WO = HID * KW;
constexpr int NW_W = NW_WQ + NW_WK + NW_WV + NW_WO;
constexpr int NW_HS = M * KW;

__global__ void pack_w_kernel(const float* __restrict__ Wq, const float* __restrict__ Wk,
                              const float* __restrict__ Wv, const float* __restrict__ Wo) {
    int i = blockIdx.x * blockDim.x + threadIdx.x;
    if (i >= NW_W) return;
    const float* src;
    uint32_t* dst;
    int j = i;
    if (j < NW_WQ) { src = Wq; dst = g_wqh; }
    else if ((j -= NW_WQ) < NW_WK) { src = Wk; dst = g_wkh; }
    else if ((j -= NW_WK) < NW_WV) { src = Wv; dst = g_wvh; }
    else { j -= NW_WV; src = Wo; dst = g_woh; }
    const float2 v = *(const float2*)(src + 2 * (size_t)j);
    dst[j] = cvt2h(v.x, v.y);
}
__global__ void pack_hs_kernel(const float* __restrict__ hs) {
    int j = blockIdx.x * blockDim.x + threadIdx.x;
    if (j >= NW_HS) return;
    const float2 v = *(const float2*)(hs + 2 * (size_t)j);
    g_hsh[j] = cvt2h(v.x, v.y);
}

// ================= fp16 GEMM, 4-stage cp.async (R14) =================
constexpr int ROW_W = 20;
constexpr int TILE_W = 128 * ROW_W;
constexpr int STAGE_W = 2 * TILE_W;
constexpr int NSTAGE = 4;
constexpr int GEMM_SMEM = NSTAGE * STAGE_W * 4;  // 81920 B
constexpr int T_A = 0, T_B = TILE_W;

__device__ __forceinline__ void gemm_body(
    const uint32_t* __restrict__ A, const uint32_t* __restrict__ Bw,
    const float* __restrict__ bias, float* __restrict__ C,
    int N, int m0, int n0, uint32_t* smw, uint32_t swb)
{
    const int tid = threadIdx.x;
    const int lane = tid & 31;
    const int w = tid >> 5;
    const int wm = w & 1, wn = w >> 1;
    const int NIT = KW / 16;

    float acc[4][4][4];
#pragma unroll
    for (int mt = 0; mt < 4; mt++)
#pragma unroll
        for (int nt = 0; nt < 4; nt++)
#pragma unroll
            for (int r = 0; r < 4; r++) acc[mt][nt][r] = 0.f;

    auto cpstage = [&](int it, int st) {
        const uint32_t ad = swb + (st * STAGE_W + T_A) * 4;
        const uint32_t bd = swb + (st * STAGE_W + T_B) * 4;
        const int k0 = it * 16;
#pragma unroll
        for (int i = 0; i < 2; i++) {
            const int idx = tid + i * 256;
            const int r = idx >> 2, c = idx & 3;
            CP16(ad + (r * ROW_W + c * 4) * 4, A + (size_t)(m0 + r) * KW + k0 + c * 4);
            CP16(bd + (r * ROW_W + c * 4) * 4, Bw + (size_t)(n0 + r) * KW + k0 + c * 4);
        }
    };

#pragma unroll
    for (int s = 0; s < NSTAGE - 1; s++) {
        cpstage(s, s);
        CP_COMMIT();
    }

    const int arow = wm * 64 + (lane >> 2);
    const int brow = wn * 32 + (lane >> 2);
    const int kq = lane & 3;

    for (int it = 0; it < NIT; it++) {
        if (it + NSTAGE - 1 < NIT) cpstage(it + NSTAGE - 1, (it + NSTAGE - 1) & 3);
        CP_COMMIT();
        CP_WAIT3();
        __syncthreads();
        uint32_t* buf = smw + (it & 3) * STAGE_W;

#pragma unroll
        for (int ks = 0; ks < 2; ks++) {
            const int kw = ks * 8 + kq;
            uint32_t ah[4][4], bh[4][2];
#pragma unroll
            for (int mt = 0; mt < 4; mt++) {
                const int base = T_A + (arow + mt * 16) * ROW_W + kw;
                ah[mt][0] = buf[base];
                ah[mt][1] = buf[base + 8 * ROW_W];
                ah[mt][2] = buf[base + 4];
                ah[mt][3] = buf[base + 8 * ROW_W + 4];
            }
#pragma unroll
            for (int nt = 0; nt < 4; nt++) {
                const int base = T_B + (brow + nt * 8) * ROW_W + kw;
                bh[nt][0] = buf[base];
                bh[nt][1] = buf[base + 4];
            }
#pragma unroll
            for (int mt = 0; mt < 4; mt++)
#pragma unroll
                for (int nt = 0; nt < 4; nt++)
                    mmah(acc[mt][nt], ah[mt], bh[nt]);
        }
        __syncthreads();
    }

#pragma unroll
    for (int mt = 0; mt < 4; mt++) {
        const int r0 = m0 + wm * 64 + mt * 16 + (lane >> 2);
#pragma unroll
        for (int nt = 0; nt < 4; nt++) {
            const int cc = n0 + wn * 32 + nt * 8 + (lane & 3) * 2;
            float b0 = 0.f, b1 = 0.f;
            if (bias) { b0 = bias[cc]; b1 = bias[cc + 1]; }
            *(float2*)(C + (size_t)r0 * N + cc) =
                make_float2(acc[mt][nt][0] + b0, acc[mt][nt][1] + b1);
            *(float2*)(C + (size_t)(r0 + 8) * N + cc) =
                make_float2(acc[mt][nt][2] + b0, acc[mt][nt][3] + b1);
        }
    }
}

__global__ __launch_bounds__(256, 1) void gemm_qkv(
    const float* __restrict__ bq, const float* __restrict__ bk,
    const float* __restrict__ bv,
    float* __restrict__ qp, float* __restrict__ kp, float* __restrict__ vp)
{
    extern __shared__ uint32_t smw[];
    const uint32_t swb = smem_u32(smw);
    const int bx = blockIdx.x;
    const int m0 = blockIdx.y * 128;
    if (bx < 16) {
        gemm_body(g_hsh, g_wqh, bq, qp, NH * HD, m0, bx * 128, smw, swb);
    } else if (bx < 20) {
        gemm_body(g_hsh, g_wkh, bk, kp, NKV * HD, m0, (bx - 16) * 128, smw, swb);
    } else {
        gemm_body(g_hsh, g_wvh, bv, vp, NKV * HD, m0, (bx - 20) * 128, smw, swb);
    }
}

__global__ __launch_bounds__(256, 1) void gemm_o(float* __restrict__ C) {
    extern __shared__ uint32_t smw[];
    const uint32_t swb = smem_u32(smw);
    gemm_body(g_ah, g_woh, nullptr, C, HID, blockIdx.y * 128, blockIdx.x * 128, smw, swb);
}

// ---------------- RoPE apply: pure fp32 via table ----------------
__global__ void rope_apply_kernel() {
    const int total = B * S * (NH + NKV) * 32;
    int idx = blockIdx.x * blockDim.x + threadIdx.x;
    if (idx >= total) return;
    const int p2 = idx & 31;
    const int p = p2 * 2;
    const int h = (idx >> 5) % (NH + NKV);
    const int rem = (idx >> 5) / (NH + NKV);
    const int s = rem % S;
    const int b = rem / S;
    const float c0 = g_cos[s * 64 + p], sn0 = g_sin[s * 64 + p];
    const float c1 = g_cos[s * 64 + p + 1], sn1 = g_sin[s * 64 + p + 1];
    if (h < NH) {
        const float* base = g_q + ((size_t)((b * S + s) * NH + h)) * HD;
        const float x0 = base[p], x1 = base[p + 1];
        const float y0 = base[p + 64], y1 = base[p + 65];
        const float scale = 0.08838834764831845f;
        uint32_t* qo = g_qh + ((size_t)((b * S + s) * NH + h)) * 64;
        qo[p2] = cvt2h((x0 * c0 - y0 * sn0) * scale, (x1 * c1 - y1 * sn1) * scale);
        qo[32 + p2] = cvt2h((y0 * c0 + x0 * sn0) * scale, (y1 * c1 + x1 * sn1) * scale);
    } else {
        const int kh = h - NH;
        const float* base = g_k + ((size_t)((b * S + s) * NKV + kh)) * HD;
        const float x0 = base[p], x1 = base[p + 1];
        const float y0 = base[p + 64], y1 = base[p + 65];
        uint32_t* ko = g_kh + ((size_t)((b * NKV + kh) * S + s)) * 64;
        ko[p2] = cvt2h(x0 * c0 - y0 * sn0, x1 * c1 - y1 * sn1);
        ko[32 + p2] = cvt2h(y0 * c0 + x0 * sn0, y1 * c1 + x1 * sn1);
    }
}

// ---------------- V: fp32 -> fp16 pair-packed ----------------
__global__ void vconv_kernel() {
    const int total = B * NKV * (S / 2) * 32;
    int idx = blockIdx.x * blockDim.x + threadIdx.x;
    if (idx >= total) return;
    const int c = idx & 31, d0 = c * 4;
    const int kwp = (idx >> 5) % (S / 2);
    const int t2 = (idx >> 5) / (S / 2);
    const int kh = t2 % NKV, b = t2 / NKV;
    const float* base = g_v + ((size_t)((b * S + 2 * kwp) * NKV + kh)) * HD + d0;
    const float4 va = *(const float4*)base;
    const float4 vb = *(const float4*)(base + (size_t)NKV * HD);
    uint32_t* vo = g_vh + ((size_t)((b * NKV + kh) * (S / 2) + kwp)) * 128 + d0;
    *(uint4*)vo = make_uint4(cvt2h(va.x, vb.x), cvt2h(va.y, vb.y),
                             cvt2h(va.z, vb.z), cvt2h(va.w, vb.w));
}

// ================= Flash attention (R11/R14, fp16 out) =================
constexpr int QT = 64, KT = 64;
constexpr int QROW = 68, KROW = 68, VROW = 136;
constexpr int A_Q = 0;
constexpr int A_K0 = A_Q + QT * QROW;
constexpr int A_V0 = A_K0 + 2 * KT * KROW;
constexpr int ATTN_SMEM = (A_V0 + 2 * 32 * VROW) * 4;  // 87040 B

__global__ __launch_bounds__(128, 2) void attn_mma() {
    extern __shared__ uint32_t sw[];
    const uint32_t swb = smem_u32(sw);
    const int q0 = (gridDim.x - 1 - blockIdx.x) * QT;
    const int h = blockIdx.y, b = blockIdx.z;
    const int kh = h >> 2;
    const int tid = threadIdx.x;
    const int lane = tid & 31, w = tid >> 5;
    const int r4 = lane >> 2, cq = lane & 3;

    const uint32_t* kbase = g_kh + ((size_t)(b * NKV + kh)) * S * 64;
    const uint32_t* vbase = g_vh + ((size_t)(b * NKV + kh)) * (S / 2) * 128;

    auto copyKV = [&](int t, int st) {
        const uint32_t kdst0 = swb + (A_K0 + st * KT * KROW) * 4;
        const uint32_t vdst0 = swb + (A_V0 + st * 32 * VROW) * 4;
        const uint32_t* kg = kbase + (size_t)t * KT * 64;
        const uint32_t* vg = vbase + (size_t)t * 32 * 128;
#pragma unroll
        for (int i = 0; i < 8; i++) {
            const int c = tid + i * 128;
            const int kr = c >> 4, kc = c & 15;
            CP16(kdst0 + (kr * KROW + kc * 4) * 4, kg + kr * 64 + kc * 4);
            const int vr = c >> 5, vc = c & 31;
            CP16(vdst0 + (vr * VROW + vc * 4) * 4, vg + vr * 128 + vc * 4);
        }
    };

    {
#pragma unroll
        for (int i = 0; i < 8; i++) {
            const int c = tid + i * 128;
            const int r = c >> 4, cc = c & 15;
            CP16(swb + (A_Q + r * QROW + cc * 4) * 4,
                 g_qh + ((size_t)((b * S + q0 + r) * NH + h)) * 64 + cc * 4);
        }
        copyKV(0, 0);
        CP_COMMIT();
    }

    float o[16][4];
#pragma unroll
    for (int nt = 0; nt < 16; nt++)
#pragma unroll
        for (int r = 0; r < 4; r++) o[nt][r] = 0.f;
    float m0 = -1e30f, m1 = -1e30f, l0 = 0.f, l1 = 0.f;

    const int ntiles = (q0 >> 6) + 1;

    for (int t = 0; t < ntiles; t++) {
        if (t + 1 < ntiles) {
            copyKV(t + 1, (t + 1) & 1);
            CP_COMMIT();
            CP_WAIT1();
        } else {
            CP_WAIT0();
        }
        __syncthreads();
        const int kb = A_K0 + (t & 1) * KT * KROW;
        const int vb = A_V0 + (t & 1) * 32 * VROW;

        float sc[8][4];
#pragma unroll
        for (int nt = 0; nt < 8; nt++)
#pragma unroll
            for (int r = 0; r < 4; r++) sc[nt][r] = 0.f;
#pragma unroll
        for (int ks = 0; ks < 8; ks++) {
            uint32_t ah[4];
            const int base = A_Q + (w * 16 + r4) * QROW + ks * 8 + cq;
            ah[0] = sw[base];
            ah[1] = sw[base + 8 * QROW];
            ah[2] = sw[base + 4];
            ah[3] = sw[base + 8 * QROW + 4];
#pragma unroll
            for (int nt = 0; nt < 8; nt++) {
                const int nb = kb + (nt * 8 + r4) * KROW + ks * 8 + cq;
                uint32_t bh[2] = {sw[nb], sw[nb + 4]};
                mmah(sc[nt], ah, bh);
            }
        }
        if (t == ntiles - 1) {
            const int n0 = t * KT;
            const int row0 = q0 + w * 16 + r4, row1 = row0 + 8;
#pragma unroll
            for (int nt = 0; nt < 8; nt++) {
                const int col0 = n0 + nt * 8 + 2 * cq;
                if (col0 > row0) sc[nt][0] = -1e30f;
                if (col0 + 1 > row0) sc[nt][1] = -1e30f;
                if (col0 > row1) sc[nt][2] = -1e30f;
                if (col0 + 1 > row1) sc[nt][3] = -1e30f;
            }
        }
        float rx0 = -1e30f, rx1 = -1e30f;
#pragma unroll
        for (int nt = 0; nt < 8; nt++) {
            rx0 = fmaxf(rx0, fmaxf(sc[nt][0], sc[nt][1]));
            rx1 = fmaxf(rx1, fmaxf(sc[nt][2], sc[nt][3]));
        }
        rx0 = fmaxf(rx0, __shfl_xor_sync(0xffffffffu, rx0, 1));
        rx0 = fmaxf(rx0, __shfl_xor_sync(0xffffffffu, rx0, 2));
        rx1 = fmaxf(rx1, __shfl_xor_sync(0xffffffffu, rx1, 1));
        rx1 = fmaxf(rx1, __shfl_xor_sync(0xffffffffu, rx1, 2));
        const float mn0 = fmaxf(m0, rx0), mn1 = fmaxf(m1, rx1);
        const float f0 = __expf(m0 - mn0), f1 = __expf(m1 - mn1);
        float rs0 = 0.f, rs1 = 0.f;
#pragma unroll
        for (int nt = 0; nt < 8; nt++) {
            sc[nt][0] = __expf(sc[nt][0] - mn0);
            sc[nt][1] = __expf(sc[nt][1] - mn0);
            sc[nt][2] = __expf(sc[nt][2] - mn1);
            sc[nt][3] = __expf(sc[nt][3] - mn1);
            rs0 += sc[nt][0] + sc[nt][1];
            rs1 += sc[nt][2] + sc[nt][3];
        }
        rs0 += __shfl_xor_sync(0xffffffffu, rs0, 1);
        rs0 += __shfl_xor_sync(0xffffffffu, rs0, 2);
        rs1 += __shfl_xor_sync(0xffffffffu, rs1, 1);
        rs1 += __shfl_xor_sync(0xffffffffu, rs1, 2);
        l0 = l0 * f0 + rs0;
        l1 = l1 * f1 + rs1;
        m0 = mn0; m1 = mn1;
#pragma unroll
        for (int nt = 0; nt < 16; nt++) {
            o[nt][0] *= f0; o[nt][1] *= f0;
            o[nt][2] *= f1; o[nt][3] *= f1;
        }
#pragma unroll
        for (int ks = 0; ks < 4; ks++) {
            uint32_t ah[4];
            ah[0] = cvt2h(sc[2 * ks][0], sc[2 * ks][1]);
            ah[1] = cvt2h(sc[2 * ks][2], sc[2 * ks][3]);
            ah[2] = cvt2h(sc[2 * ks + 1][0], sc[2 * ks + 1][1]);
            ah[3] = cvt2h(sc[2 * ks + 1][2], sc[2 * ks + 1][3]);
#pragma unroll
            for (int nt = 0; nt < 16; nt++) {
                const int vb0 = vb + (ks * 8 + cq) * VROW + nt * 8 + r4;
                uint32_t bh[2] = {sw[vb0], sw[vb0 + 4 * VROW]};
                mmah(o[nt], ah, bh);
            }
        }
        __syncthreads();
    }

    const float i0 = 1.0f / l0, i1 = 1.0f / l1;
    uint32_t* a0 = g_ah + (size_t)(b * S + q0 + w * 16 + r4) * KW + h * 64;
    uint32_t* a1 = g_ah + (size_t)(b * S + q0 + w * 16 + r4 + 8) * KW + h * 64;
#pragma unroll
    for (int nt = 0; nt < 16; nt++) {
        a0[nt * 4 + cq] = cvt2h(o[nt][0] * i0, o[nt][1] * i0);
        a1[nt * 4 + cq] = cvt2h(o[nt][2] * i1, o[nt][3] * i1);
    }
}

// ---------------- launch ----------------
extern "C" void kernel_launch(void* const* d_in, const int* in_sizes, int n_in,
                              void* d_out, int out_size) {
    const float* hs = (const float*)d_in[0];
    // d_in[1] = attention_mask: pure causal -> applied analytically
    const float* Wq = (const float*)d_in[2];
    const float* bq = (const float*)d_in[3];
    const float* Wk = (const float*)d_in[4];
    const float* bk = (const float*)d_in[5];
    const float* Wv = (const float*)d_in[6];
    const float* bv = (const float*)d_in[7];
    const float* Wo = (const float*)d_in[8];
    float* out = (float*)d_out;

    float *qp, *kp, *vp;
    cudaGetSymbolAddress((void**)&qp, g_q);
    cudaGetSymbolAddress((void**)&kp, g_k);
    cudaGetSymbolAddress((void**)&vp, g_v);

    cudaFuncSetAttribute(gemm_qkv, cudaFuncAttributeMaxDynamicSharedMemorySize, GEMM_SMEM);
    cudaFuncSetAttribute(gemm_o, cudaFuncAttributeMaxDynamicSharedMemorySize, GEMM_SMEM);
    cudaFuncSetAttribute(attn_mma, cudaFuncAttributeMaxDynamicSharedMemorySize, ATTN_SMEM);

    // #1: RoPE table (all FP64 confined here: 131K threads, once)
    rope_table_kernel<<<(S * 64 + 255) / 256, 256>>>();
    // #2, #3: pack fp32 -> fp16
    pack_w_kernel<<<(NW_W + 255) / 256, 256>>>(Wq, Wk, Wv, Wo);
    pack_hs_kernel<<<(NW_HS + 255) / 256, 256>>>(hs);
    // #4: QKV projection  (position 4 -> gets the ncu profile next round)
    gemm_qkv<<<dim3(24, M / 128), 256, GEMM_SMEM>>>(bq, bk, bv, qp, kp, vp);
    // #5: RoPE apply (pure fp32, table lookups)
    const int rope_total = B * S * (NH + NKV) * 32;
    rope_apply_kernel<<<(rope_total + 255) / 256, 256>>>();
    // #6: V pack
    const int vconv_total = B * NKV * (S / 2) * 32;
    vconv_kernel<<<(vconv_total + 255) / 256, 256>>>();
    // #7: attention
    attn_mma<<<dim3(S / QT, NH, B), 128, ATTN_SMEM>>>();
    // #8: output projection
    gemm_o<<<dim3(HID / 128, M / 128), 256, GEMM_SMEM>>>(out);
}

// round 16
// speedup vs baseline: 3.0511x; 1.1015x over previous
#include <cuda_runtime.h>
#include <cstdint>

// Problem constants
constexpr int B = 2, S = 2048, HID = 2048, NH = 16, NKV = 4, HD = 128;
constexpr int M = B * S;
constexpr int KW = HID / 2;  // 1024 fp16-pair words per GEMM row (K=2048)

// fp32 scratch (rope/vconv inputs)
__device__ float g_q[(size_t)B * S * NH * HD];
__device__ float g_k[(size_t)B * S * NKV * HD];
__device__ float g_v[(size_t)B * S * NKV * HD];
// RoPE tables (fp32, computed once in double)
__device__ float g_cos[(size_t)S * 64];
__device__ float g_sin[(size_t)S * 64];
// fp16 packed (1 word = 2 fp16) GEMM operands
__device__ uint32_t g_hsh[(size_t)M * KW];
__device__ uint32_t g_wqh[(size_t)(NH * HD) * KW];
__device__ uint32_t g_wkh[(size_t)(NKV * HD) * KW];
__device__ uint32_t g_wvh[(size_t)(NKV * HD) * KW];
__device__ uint32_t g_woh[(size_t)HID * KW];
__device__ uint32_t g_ah[(size_t)M * KW];
// fp16 packed attention-ready buffers
__device__ uint32_t g_qh[(size_t)B * S * NH * 64];
__device__ uint32_t g_kh[(size_t)B * NKV * S * 64];
__device__ uint32_t g_vh[(size_t)B * NKV * (S / 2) * 128];

// ---------------- helpers ----------------
__device__ __forceinline__ uint32_t cvt2h(float lo_e, float hi_e) {
    uint32_t r;
    asm("cvt.rn.f16x2.f32 %0, %1, %2;" : "=r"(r) : "f"(hi_e), "f"(lo_e));
    return r;
}
__device__ __forceinline__ void mmah(float* c, const uint32_t* a, const uint32_t* b) {
    asm volatile(
        "mma.sync.aligned.m16n8k16.row.col.f32.f16.f16.f32 "
        "{%0,%1,%2,%3}, {%4,%5,%6,%7}, {%8,%9}, {%0,%1,%2,%3};"
        : "+f"(c[0]), "+f"(c[1]), "+f"(c[2]), "+f"(c[3])
        : "r"(a[0]), "r"(a[1]), "r"(a[2]), "r"(a[3]), "r"(b[0]), "r"(b[1]));
}
__device__ __forceinline__ uint32_t smem_u32(const void* p) {
    uint32_t a;
    asm("{ .reg .u64 t; cvta.to.shared.u64 t, %1; cvt.u32.u64 %0, t; }" : "=r"(a) : "l"(p));
    return a;
}
#define CP16(dst, src) \
    asm volatile("cp.async.cg.shared.global [%0], [%1], 16;" :: "r"(dst), "l"(src) : "memory")
#define CP_COMMIT() asm volatile("cp.async.commit_group;" ::: "memory")
#define CP_WAIT0() asm volatile("cp.async.wait_group 0;" ::: "memory")
#define CP_WAIT1() asm volatile("cp.async.wait_group 1;" ::: "memory")
#define CP_WAIT2() asm volatile("cp.async.wait_group 2;" ::: "memory")

// ---------------- RoPE table: double math ONCE per (s,p) ----------------
__global__ void rope_table_kernel() {
    int idx = blockIdx.x * blockDim.x + threadIdx.x;
    if (idx >= S * 64) return;
    const int p = idx & 63, s = idx >> 6;
    const double ang = (double)s * pow(10000.0, -(double)p / 64.0);
    double sd, cd;
    sincos(ang, &sd, &cd);
    g_cos[idx] = (float)cd;
    g_sin[idx] = (float)sd;
}

// ---------------- fp32 -> fp16 pack ----------------
constexpr int NW_WQ = NH * HD * KW;
constexpr int NW_WK = NKV * HD * KW;
constexpr int NW_WV = NW_WK;
constexpr int NW_WO = HID * KW;
constexpr int NW_W = NW_WQ + NW_WK + NW_WV + NW_WO;
constexpr int NW_HS = M * KW;

__global__ void pack_w_kernel(const float* __restrict__ Wq, const float* __restrict__ Wk,
                              const float* __restrict__ Wv, const float* __restrict__ Wo) {
    int i = blockIdx.x * blockDim.x + threadIdx.x;
    if (i >= NW_W) return;
    const float* src;
    uint32_t* dst;
    int j = i;
    if (j < NW_WQ) { src = Wq; dst = g_wqh; }
    else if ((j -= NW_WQ) < NW_WK) { src = Wk; dst = g_wkh; }
    else if ((j -= NW_WK) < NW_WV) { src = Wv; dst = g_wvh; }
    else { j -= NW_WV; src = Wo; dst = g_woh; }
    const float2 v = *(const float2*)(src + 2 * (size_t)j);
    dst[j] = cvt2h(v.x, v.y);
}
__global__ void pack_hs_kernel(const float* __restrict__ hs) {
    int j = blockIdx.x * blockDim.x + threadIdx.x;
    if (j >= NW_HS) return;
    const float2 v = *(const float2*)(hs + 2 * (size_t)j);
    g_hsh[j] = cvt2h(v.x, v.y);
}

// ================= fp16 GEMM, 4-stage cp.async, single barrier/iter =================
constexpr int ROW_W = 20;
constexpr int TILE_W = 128 * ROW_W;
constexpr int STAGE_W = 2 * TILE_W;
constexpr int NSTAGE = 4;
constexpr int GEMM_SMEM = NSTAGE * STAGE_W * 4;  // 81920 B (2 CTAs: 160K < 228K)
constexpr int T_A = 0, T_B = TILE_W;

__device__ __forceinline__ void gemm_body(
    const uint32_t* __restrict__ A, const uint32_t* __restrict__ Bw,
    const float* __restrict__ bias, float* __restrict__ C,
    int N, int m0, int n0, uint32_t* smw, uint32_t swb)
{
    const int tid = threadIdx.x;
    const int lane = tid & 31;
    const int w = tid >> 5;
    const int wm = w & 1, wn = w >> 1;
    const int NIT = KW / 16;

    float acc[4][4][4];
#pragma unroll
    for (int mt = 0; mt < 4; mt++)
#pragma unroll
        for (int nt = 0; nt < 4; nt++)
#pragma unroll
            for (int r = 0; r < 4; r++) acc[mt][nt][r] = 0.f;

    auto cpstage = [&](int it, int st) {
        const uint32_t ad = swb + (st * STAGE_W + T_A) * 4;
        const uint32_t bd = swb + (st * STAGE_W + T_B) * 4;
        const int k0 = it * 16;
#pragma unroll
        for (int i = 0; i < 2; i++) {
            const int idx = tid + i * 256;
            const int r = idx >> 2, c = idx & 3;
            CP16(ad + (r * ROW_W + c * 4) * 4, A + (size_t)(m0 + r) * KW + k0 + c * 4);
            CP16(bd + (r * ROW_W + c * 4) * 4, Bw + (size_t)(n0 + r) * KW + k0 + c * 4);
        }
    };

#pragma unroll
    for (int s = 0; s < NSTAGE - 1; s++) {
        cpstage(s, s);
        CP_COMMIT();
    }

    const int arow = wm * 64 + (lane >> 2);
    const int brow = wn * 32 + (lane >> 2);
    const int kq = lane & 3;

    for (int it = 0; it < NIT; it++) {
        // Single barrier per iter: wait for stage `it` (commits before this
        // wait = 3 + it; need groups 0..it done => <=2 in flight), sync, THEN
        // issue the prefetch for it+3. A fast warp can only issue the write to
        // stage (it+4)&3 == it&3 after the *next* barrier, which requires all
        // warps done reading stage it&3 — so no post-compute barrier needed.
        CP_WAIT2();
        __syncthreads();
        if (it + NSTAGE - 1 < NIT) cpstage(it + NSTAGE - 1, (it + NSTAGE - 1) & 3);
        CP_COMMIT();
        uint32_t* buf = smw + (it & 3) * STAGE_W;

#pragma unroll
        for (int ks = 0; ks < 2; ks++) {
            const int kw = ks * 8 + kq;
            uint32_t ah[4][4], bh[4][2];
#pragma unroll
            for (int mt = 0; mt < 4; mt++) {
                const int base = T_A + (arow + mt * 16) * ROW_W + kw;
                ah[mt][0] = buf[base];
                ah[mt][1] = buf[base + 8 * ROW_W];
                ah[mt][2] = buf[base + 4];
                ah[mt][3] = buf[base + 8 * ROW_W + 4];
            }
#pragma unroll
            for (int nt = 0; nt < 4; nt++) {
                const int base = T_B + (brow + nt * 8) * ROW_W + kw;
                bh[nt][0] = buf[base];
                bh[nt][1] = buf[base + 4];
            }
#pragma unroll
            for (int mt = 0; mt < 4; mt++)
#pragma unroll
                for (int nt = 0; nt < 4; nt++)
                    mmah(acc[mt][nt], ah[mt], bh[nt]);
        }
    }

#pragma unroll
    for (int mt = 0; mt < 4; mt++) {
        const int r0 = m0 + wm * 64 + mt * 16 + (lane >> 2);
#pragma unroll
        for (int nt = 0; nt < 4; nt++) {
            const int cc = n0 + wn * 32 + nt * 8 + (lane & 3) * 2;
            float b0 = 0.f, b1 = 0.f;
            if (bias) { b0 = bias[cc]; b1 = bias[cc + 1]; }
            *(float2*)(C + (size_t)r0 * N + cc) =
                make_float2(acc[mt][nt][0] + b0, acc[mt][nt][1] + b1);
            *(float2*)(C + (size_t)(r0 + 8) * N + cc) =
                make_float2(acc[mt][nt][2] + b0, acc[mt][nt][3] + b1);
        }
    }
}

__global__ __launch_bounds__(256, 2) void gemm_qkv(
    const float* __restrict__ bq, const float* __restrict__ bk,
    const float* __restrict__ bv,
    float* __restrict__ qp, float* __restrict__ kp, float* __restrict__ vp)
{
    extern __shared__ uint32_t smw[];
    const uint32_t swb = smem_u32(smw);
    const int bx = blockIdx.x;
    const int m0 = blockIdx.y * 128;
    if (bx < 16) {
        gemm_body(g_hsh, g_wqh, bq, qp, NH * HD, m0, bx * 128, smw, swb);
    } else if (bx < 20) {
        gemm_body(g_hsh, g_wkh, bk, kp, NKV * HD, m0, (bx - 16) * 128, smw, swb);
    } else {
        gemm_body(g_hsh, g_wvh, bv, vp, NKV * HD, m0, (bx - 20) * 128, smw, swb);
    }
}

__global__ __launch_bounds__(256, 2) void gemm_o(float* __restrict__ C) {
    extern __shared__ uint32_t smw[];
    const uint32_t swb = smem_u32(smw);
    gemm_body(g_ah, g_woh, nullptr, C, HID, blockIdx.y * 128, blockIdx.x * 128, smw, swb);
}

// ---------------- RoPE apply: pure fp32 via table ----------------
__global__ void rope_apply_kernel() {
    const int total = B * S * (NH + NKV) * 32;
    int idx = blockIdx.x * blockDim.x + threadIdx.x;
    if (idx >= total) return;
    const int p2 = idx & 31;
    const int p = p2 * 2;
    const int h = (idx >> 5) % (NH + NKV);
    const int rem = (idx >> 5) / (NH + NKV);
    const int s = rem % S;
    const int b = rem / S;
    const float c0 = g_cos[s * 64 + p], sn0 = g_sin[s * 64 + p];
    const float c1 = g_cos[s * 64 + p + 1], sn1 = g_sin[s * 64 + p + 1];
    if (h < NH) {
        const float* base = g_q + ((size_t)((b * S + s) * NH + h)) * HD;
        const float x0 = base[p], x1 = base[p + 1];
        const float y0 = base[p + 64], y1 = base[p + 65];
        const float scale = 0.08838834764831845f;
        uint32_t* qo = g_qh + ((size_t)((b * S + s) * NH + h)) * 64;
        qo[p2] = cvt2h((x0 * c0 - y0 * sn0) * scale, (x1 * c1 - y1 * sn1) * scale);
        qo[32 + p2] = cvt2h((y0 * c0 + x0 * sn0) * scale, (y1 * c1 + x1 * sn1) * scale);
    } else {
        const int kh = h - NH;
        const float* base = g_k + ((size_t)((b * S + s) * NKV + kh)) * HD;
        const float x0 = base[p], x1 = base[p + 1];
        const float y0 = base[p + 64], y1 = base[p + 65];
        uint32_t* ko = g_kh + ((size_t)((b * NKV + kh) * S + s)) * 64;
        ko[p2] = cvt2h(x0 * c0 - y0 * sn0, x1 * c1 - y1 * sn1);
        ko[32 + p2] = cvt2h(y0 * c0 + x0 * sn0, y1 * c1 + x1 * sn1);
    }
}

// ---------------- V: fp32 -> fp16 pair-packed ----------------
__global__ void vconv_kernel() {
    const int total = B * NKV * (S / 2) * 32;
    int idx = blockIdx.x * blockDim.x + threadIdx.x;
    if (idx >= total) return;
    const int c = idx & 31, d0 = c * 4;
    const int kwp = (idx >> 5) % (S / 2);
    const int t2 = (idx >> 5) / (S / 2);
    const int kh = t2 % NKV, b = t2 / NKV;
    const float* base = g_v + ((size_t)((b * S + 2 * kwp) * NKV + kh)) * HD + d0;
    const float4 va = *(const float4*)base;
    const float4 vb = *(const float4*)(base + (size_t)NKV * HD);
    uint32_t* vo = g_vh + ((size_t)((b * NKV + kh) * (S / 2) + kwp)) * 128 + d0;
    *(uint4*)vo = make_uint4(cvt2h(va.x, vb.x), cvt2h(va.y, vb.y),
                             cvt2h(va.z, vb.z), cvt2h(va.w, vb.w));
}

// ================= Flash attention (R11/R14, fp16 out) =================
constexpr int QT = 64, KT = 64;
constexpr int QROW = 68, KROW = 68, VROW = 136;
constexpr int A_Q = 0;
constexpr int A_K0 = A_Q + QT * QROW;
constexpr int A_V0 = A_K0 + 2 * KT * KROW;
constexpr int ATTN_SMEM = (A_V0 + 2 * 32 * VROW) * 4;  // 87040 B

__global__ __launch_bounds__(128, 2) void attn_mma() {
    extern __shared__ uint32_t sw[];
    const uint32_t swb = smem_u32(sw);
    const int q0 = (gridDim.x - 1 - blockIdx.x) * QT;
    const int h = blockIdx.y, b = blockIdx.z;
    const int kh = h >> 2;
    const int tid = threadIdx.x;
    const int lane = tid & 31, w = tid >> 5;
    const int r4 = lane >> 2, cq = lane & 3;

    const uint32_t* kbase = g_kh + ((size_t)(b * NKV + kh)) * S * 64;
    const uint32_t* vbase = g_vh + ((size_t)(b * NKV + kh)) * (S / 2) * 128;

    auto copyKV = [&](int t, int st) {
        const uint32_t kdst0 = swb + (A_K0 + st * KT * KROW) * 4;
        const uint32_t vdst0 = swb + (A_V0 + st * 32 * VROW) * 4;
        const uint32_t* kg = kbase + (size_t)t * KT * 64;
        const uint32_t* vg = vbase + (size_t)t * 32 * 128;
#pragma unroll
        for (int i = 0; i < 8; i++) {
            const int c = tid + i * 128;
            const int kr = c >> 4, kc = c & 15;
            CP16(kdst0 + (kr * KROW + kc * 4) * 4, kg + kr * 64 + kc * 4);
            const int vr = c >> 5, vc = c & 31;
            CP16(vdst0 + (vr * VROW + vc * 4) * 4, vg + vr * 128 + vc * 4);
        }
    };

    {
#pragma unroll
        for (int i = 0; i < 8; i++) {
            const int c = tid + i * 128;
            const int r = c >> 4, cc = c & 15;
            CP16(swb + (A_Q + r * QROW + cc * 4) * 4,
                 g_qh + ((size_t)((b * S + q0 + r) * NH + h)) * 64 + cc * 4);
        }
        copyKV(0, 0);
        CP_COMMIT();
    }

    float o[16][4];
#pragma unroll
    for (int nt = 0; nt < 16; nt++)
#pragma unroll
        for (int r = 0; r < 4; r++) o[nt][r] = 0.f;
    float m0 = -1e30f, m1 = -1e30f, l0 = 0.f, l1 = 0.f;

    const int ntiles = (q0 >> 6) + 1;

    for (int t = 0; t < ntiles; t++) {
        if (t + 1 < ntiles) {
            copyKV(t + 1, (t + 1) & 1);
            CP_COMMIT();
            CP_WAIT1();
        } else {
            CP_WAIT0();
        }
        __syncthreads();
        const int kb = A_K0 + (t & 1) * KT * KROW;
        const int vb = A_V0 + (t & 1) * 32 * VROW;

        float sc[8][4];
#pragma unroll
        for (int nt = 0; nt < 8; nt++)
#pragma unroll
            for (int r = 0; r < 4; r++) sc[nt][r] = 0.f;
#pragma unroll
        for (int ks = 0; ks < 8; ks++) {
            uint32_t ah[4];
            const int base = A_Q + (w * 16 + r4) * QROW + ks * 8 + cq;
            ah[0] = sw[base];
            ah[1] = sw[base + 8 * QROW];
            ah[2] = sw[base + 4];
            ah[3] = sw[base + 8 * QROW + 4];
#pragma unroll
            for (int nt = 0; nt < 8; nt++) {
                const int nb = kb + (nt * 8 + r4) * KROW + ks * 8 + cq;
                uint32_t bh[2] = {sw[nb], sw[nb + 4]};
                mmah(sc[nt], ah, bh);
            }
        }
        if (t == ntiles - 1) {
            const int n0 = t * KT;
            const int row0 = q0 + w * 16 + r4, row1 = row0 + 8;
#pragma unroll
            for (int nt = 0; nt < 8; nt++) {
                const int col0 = n0 + nt * 8 + 2 * cq;
                if (col0 > row0) sc[nt][0] = -1e30f;
                if (col0 + 1 > row0) sc[nt][1] = -1e30f;
                if (col0 > row1) sc[nt][2] = -1e30f;
                if (col0 + 1 > row1) sc[nt][3] = -1e30f;
            }
        }
        float rx0 = -1e30f, rx1 = -1e30f;
#pragma unroll
        for (int nt = 0; nt < 8; nt++) {
            rx0 = fmaxf(rx0, fmaxf(sc[nt][0], sc[nt][1]));
            rx1 = fmaxf(rx1, fmaxf(sc[nt][2], sc[nt][3]));
        }
        rx0 = fmaxf(rx0, __shfl_xor_sync(0xffffffffu, rx0, 1));
        rx0 = fmaxf(rx0, __shfl_xor_sync(0xffffffffu, rx0, 2));
        rx1 = fmaxf(rx1, __shfl_xor_sync(0xffffffffu, rx1, 1));
        rx1 = fmaxf(rx1, __shfl_xor_sync(0xffffffffu, rx1, 2));
        const float mn0 = fmaxf(m0, rx0), mn1 = fmaxf(m1, rx1);
        const float f0 = __expf(m0 - mn0), f1 = __expf(m1 - mn1);
        float rs0 = 0.f, rs1 = 0.f;
#pragma unroll
        for (int nt = 0; nt < 8; nt++) {
            sc[nt][0] = __expf(sc[nt][0] - mn0);
            sc[nt][1] = __expf(sc[nt][1] - mn0);
            sc[nt][2] = __expf(sc[nt][2] - mn1);
            sc[nt][3] = __expf(sc[nt][3] - mn1);
            rs0 += sc[nt][0] + sc[nt][1];
            rs1 += sc[nt][2] + sc[nt][3];
        }
        rs0 += __shfl_xor_sync(0xffffffffu, rs0, 1);
        rs0 += __shfl_xor_sync(0xffffffffu, rs0, 2);
        rs1 += __shfl_xor_sync(0xffffffffu, rs1, 1);
        rs1 += __shfl_xor_sync(0xffffffffu, rs1, 2);
        l0 = l0 * f0 + rs0;
        l1 = l1 * f1 + rs1;
        m0 = mn0; m1 = mn1;
#pragma unroll
        for (int nt = 0; nt < 16; nt++) {
            o[nt][0] *= f0; o[nt][1] *= f0;
            o[nt][2] *= f1; o[nt][3] *= f1;
        }
#pragma unroll
        for (int ks = 0; ks < 4; ks++) {
            uint32_t ah[4];
            ah[0] = cvt2h(sc[2 * ks][0], sc[2 * ks][1]);
            ah[1] = cvt2h(sc[2 * ks][2], sc[2 * ks][3]);
            ah[2] = cvt2h(sc[2 * ks + 1][0], sc[2 * ks + 1][1]);
            ah[3] = cvt2h(sc[2 * ks + 1][2], sc[2 * ks + 1][3]);
#pragma unroll
            for (int nt = 0; nt < 16; nt++) {
                const int vb0 = vb + (ks * 8 + cq) * VROW + nt * 8 + r4;
                uint32_t bh[2] = {sw[vb0], sw[vb0 + 4 * VROW]};
                mmah(o[nt], ah, bh);
            }
        }
        __syncthreads();
    }

    const float i0 = 1.0f / l0, i1 = 1.0f / l1;
    uint32_t* a0 = g_ah + (size_t)(b * S + q0 + w * 16 + r4) * KW + h * 64;
    uint32_t* a1 = g_ah + (size_t)(b * S + q0 + w * 16 + r4 + 8) * KW + h * 64;
#pragma unroll
    for (int nt = 0; nt < 16; nt++) {
        a0[nt * 4 + cq] = cvt2h(o[nt][0] * i0, o[nt][1] * i0);
        a1[nt * 4 + cq] = cvt2h(o[nt][2] * i1, o[nt][3] * i1);
    }
}

// ---------------- launch ----------------
extern "C" void kernel_launch(void* const* d_in, const int* in_sizes, int n_in,
                              void* d_out, int out_size) {
    const float* hs = (const float*)d_in[0];
    // d_in[1] = attention_mask: pure causal -> applied analytically
    const float* Wq = (const float*)d_in[2];
    const float* bq = (const float*)d_in[3];
    const float* Wk = (const float*)d_in[4];
    const float* bk = (const float*)d_in[5];
    const float* Wv = (const float*)d_in[6];
    const float* bv = (const float*)d_in[7];
    const float* Wo = (const float*)d_in[8];
    float* out = (float*)d_out;

    float *qp, *kp, *vp;
    cudaGetSymbolAddress((void**)&qp, g_q);
    cudaGetSymbolAddress((void**)&kp, g_k);
    cudaGetSymbolAddress((void**)&vp, g_v);

    cudaFuncSetAttribute(gemm_qkv, cudaFuncAttributeMaxDynamicSharedMemorySize, GEMM_SMEM);
    cudaFuncSetAttribute(gemm_o, cudaFuncAttributeMaxDynamicSharedMemorySize, GEMM_SMEM);
    cudaFuncSetAttribute(attn_mma, cudaFuncAttributeMaxDynamicSharedMemorySize, ATTN_SMEM);

    // #1: RoPE table (FP64 confined here)
    rope_table_kernel<<<(S * 64 + 255) / 256, 256>>>();
    // #2, #3: pack fp32 -> fp16
    pack_w_kernel<<<(NW_W + 255) / 256, 256>>>(Wq, Wk, Wv, Wo);
    pack_hs_kernel<<<(NW_HS + 255) / 256, 256>>>(hs);
    // #4: QKV projection (2 CTAs/SM, single-barrier pipeline)
    gemm_qkv<<<dim3(24, M / 128), 256, GEMM_SMEM>>>(bq, bk, bv, qp, kp, vp);
    // #5: RoPE apply
    const int rope_total = B * S * (NH + NKV) * 32;
    rope_apply_kernel<<<(rope_total + 255) / 256, 256>>>();
    // #6: V pack
    const int vconv_total = B * NKV * (S / 2) * 32;
    vconv_kernel<<<(vconv_total + 255) / 256, 256>>>();
    // #7: attention
    attn_mma<<<dim3(S / QT, NH, B), 128, ATTN_SMEM>>>();
    // #8: output projection
    gemm_o<<<dim3(HID / 128, M / 128), 256, GEMM_SMEM>>>(out);
}